// round 5
// baseline (speedup 1.0000x reference)
#include <cuda_runtime.h>
#include <cstdint>

// Problem dims (fixed by the reference)
#define T_DIM 2048
#define B_DIM 16
#define D_DIM 1024
#define BD    16384            // B_DIM * D_DIM
#define M_DIM 32768            // T_DIM * B_DIM

// ---------------------------------------------------------------------------
// Scratch: alpha = sigmoid(x@Wa^T + ba), v = tanh(x@Wx^T + bv), both [M_DIM, D]
// __device__ globals (no runtime allocation allowed).
// ---------------------------------------------------------------------------
__device__ float g_alpha[(size_t)M_DIM * D_DIM];
__device__ float g_v[(size_t)M_DIM * D_DIM];

// ---------------------------------------------------------------------------
// Helpers
// ---------------------------------------------------------------------------
__device__ __forceinline__ float to_tf32(float x) {
    uint32_t u;
    asm("cvt.rna.tf32.f32 %0, %1;" : "=r"(u) : "f"(x));
    return __uint_as_float(u);
}

__device__ __forceinline__ float4 cvt4(float4 v) {
    v.x = to_tf32(v.x); v.y = to_tf32(v.y);
    v.z = to_tf32(v.z); v.w = to_tf32(v.w);
    return v;
}

__device__ __forceinline__ void ldsm4(uint32_t& d0, uint32_t& d1, uint32_t& d2,
                                      uint32_t& d3, uint32_t addr) {
    asm volatile("ldmatrix.sync.aligned.m8n8.x4.shared.b16 {%0,%1,%2,%3}, [%4];"
                 : "=r"(d0), "=r"(d1), "=r"(d2), "=r"(d3)
                 : "r"(addr) : "memory");
}

__device__ __forceinline__ void mma_tf32(float* c, const uint32_t* a,
                                         const uint32_t* b) {
    asm volatile(
        "mma.sync.aligned.m16n8k8.row.col.f32.tf32.tf32.f32 "
        "{%0,%1,%2,%3}, {%4,%5,%6,%7}, {%8,%9}, {%0,%1,%2,%3};"
        : "+f"(c[0]), "+f"(c[1]), "+f"(c[2]), "+f"(c[3])
        : "r"(a[0]), "r"(a[1]), "r"(a[2]), "r"(a[3]), "r"(b[0]), "r"(b[1]));
}

__device__ __forceinline__ float fsigmoid(float z) {
    return 1.0f / (1.0f + __expf(-z));
}
__device__ __forceinline__ float ftanh_fast(float z) {
    // tanh(z) = 1 - 2/(exp(2z)+1); saturates correctly at +-inf of __expf
    return 1.0f - 2.0f / (1.0f + __expf(2.0f * z));
}

// ---------------------------------------------------------------------------
// Dual-projection GEMM: C[m, e] = sum_d X[m,d] * W[e,d]  (+bias, +activation)
// Tile: CTA 128x128, BK=16, 8 warps (2x4), warp tile 64x32, mma m16n8k8 tf32.
// Smem layout: sA[m][k], sB[n][k], row stride 20 floats (pad 4) ->
// conflict-free ldmatrix (20r mod 32 covers distinct 4-bank chunks).
// blockIdx.x in [0,16): bit3 selects matrix (0=alpha/sigmoid, 1=v/tanh),
// low 3 bits = n-tile. Consecutive bids share the same m-tile -> x tile is
// fetched from DRAM once per wave and reused via L2.
// ---------------------------------------------------------------------------
__global__ __launch_bounds__(256) void gemm_dual_kernel(
    const float* __restrict__ X,
    const float* __restrict__ Wa, const float* __restrict__ ba,
    const float* __restrict__ Wx, const float* __restrict__ bv)
{
    __shared__ __align__(16) float sA[2][128 * 20];
    __shared__ __align__(16) float sB[2][128 * 20];

    const int mat = (int)(blockIdx.x >> 3);
    const int n0  = (int)(blockIdx.x & 7) * 128;
    const int m0  = (int)blockIdx.y * 128;

    const float* __restrict__ W    = mat ? Wx : Wa;
    const float* __restrict__ bias = mat ? bv : ba;
    float* __restrict__ outp       = mat ? g_v : g_alpha;

    const int tid  = threadIdx.x;
    const int lane = tid & 31;
    const int warp = tid >> 5;
    const int wm   = warp >> 2;   // 0..1  (64-row slab)
    const int wn   = warp & 3;    // 0..3  (32-col slab)

    // global->smem staging: each thread moves 2 float4 rows-chunks per matrix
    const int r0 = tid >> 2;      // 0..63 (and +64 for second)
    const int cq = tid & 3;       // float4 chunk within the 16-float k-slice

    const float4* __restrict__ Xv = reinterpret_cast<const float4*>(X);
    const float4* __restrict__ Wv = reinterpret_cast<const float4*>(W);

    // ldmatrix per-lane geometry
    const int rA  = ((lane >> 3) & 1) * 8 + (lane & 7);  // A: tiles 0/2 rows, 1/3 rows+8
    const int kwA = (lane >> 4) * 4;                     // A: tiles 2,3 at k+4
    const int rB  = (lane >> 4) * 8 + (lane & 7);        // B: tiles 2,3 rows+8
    const int kwB = ((lane >> 3) & 1) * 4;               // B: tiles 1,3 at k+4

    const uint32_t sA0 = (uint32_t)__cvta_generic_to_shared(&sA[0][0]);
    const uint32_t sB0 = (uint32_t)__cvta_generic_to_shared(&sB[0][0]);
    const uint32_t aBase = sA0 + (uint32_t)(((wm * 64 + rA) * 20 + kwA) * 4);
    const uint32_t bBase = sB0 + (uint32_t)(((wn * 32 + rB) * 20 + kwB) * 4);

    float acc[4][4][4];
#pragma unroll
    for (int mf = 0; mf < 4; ++mf)
#pragma unroll
        for (int nf = 0; nf < 4; ++nf)
#pragma unroll
            for (int q = 0; q < 4; ++q) acc[mf][nf][q] = 0.0f;

    float4 ra0, ra1, rb0, rb1;

    // Prologue: load k-tile 0
    ra0 = cvt4(Xv[(size_t)(m0 + r0)      * 256 + cq]);
    ra1 = cvt4(Xv[(size_t)(m0 + r0 + 64) * 256 + cq]);
    rb0 = cvt4(Wv[(size_t)(n0 + r0)      * 256 + cq]);
    rb1 = cvt4(Wv[(size_t)(n0 + r0 + 64) * 256 + cq]);
    *(float4*)&sA[0][r0 * 20 + cq * 4]        = ra0;
    *(float4*)&sA[0][(r0 + 64) * 20 + cq * 4] = ra1;
    *(float4*)&sB[0][r0 * 20 + cq * 4]        = rb0;
    *(float4*)&sB[0][(r0 + 64) * 20 + cq * 4] = rb1;
    __syncthreads();

    const int NKT = D_DIM / 16;   // 64 k-tiles
    for (int kt = 0; kt < NKT; ++kt) {
        const int buf = kt & 1;

        if (kt + 1 < NKT) {
            const int kc = (kt + 1) * 4 + cq;
            ra0 = cvt4(Xv[(size_t)(m0 + r0)      * 256 + kc]);
            ra1 = cvt4(Xv[(size_t)(m0 + r0 + 64) * 256 + kc]);
            rb0 = cvt4(Wv[(size_t)(n0 + r0)      * 256 + kc]);
            rb1 = cvt4(Wv[(size_t)(n0 + r0 + 64) * 256 + kc]);
        }

        const uint32_t ab = aBase + (uint32_t)buf * 10240u;
        const uint32_t bb = bBase + (uint32_t)buf * 10240u;
#pragma unroll
        for (int ks = 0; ks < 2; ++ks) {
            uint32_t afr[4][4];
#pragma unroll
            for (int mf = 0; mf < 4; ++mf)
                ldsm4(afr[mf][0], afr[mf][1], afr[mf][2], afr[mf][3],
                      ab + (uint32_t)(mf * 1280 + ks * 32));
            uint32_t bfr[4][2];
#pragma unroll
            for (int p = 0; p < 2; ++p)
                ldsm4(bfr[2 * p][0], bfr[2 * p][1], bfr[2 * p + 1][0],
                      bfr[2 * p + 1][1], bb + (uint32_t)(p * 1280 + ks * 32));
#pragma unroll
            for (int mf = 0; mf < 4; ++mf)
#pragma unroll
                for (int nf = 0; nf < 4; ++nf)
                    mma_tf32(acc[mf][nf], afr[mf], bfr[nf]);
        }

        if (kt + 1 < NKT) {
            const int nb = buf ^ 1;
            *(float4*)&sA[nb][r0 * 20 + cq * 4]        = ra0;
            *(float4*)&sA[nb][(r0 + 64) * 20 + cq * 4] = ra1;
            *(float4*)&sB[nb][r0 * 20 + cq * 4]        = rb0;
            *(float4*)&sB[nb][(r0 + 64) * 20 + cq * 4] = rb1;
        }
        __syncthreads();
    }

    // Epilogue: bias + activation, float2 stores
    const int g   = lane >> 2;
    const int tig = lane & 3;
#pragma unroll
    for (int mf = 0; mf < 4; ++mf) {
#pragma unroll
        for (int nf = 0; nf < 4; ++nf) {
            const int row = m0 + wm * 64 + mf * 16 + g;
            const int col = n0 + wn * 32 + nf * 8 + 2 * tig;
            const float bb0 = bias[col];
            const float bb1 = bias[col + 1];
            float z00 = acc[mf][nf][0] + bb0;
            float z01 = acc[mf][nf][1] + bb1;
            float z10 = acc[mf][nf][2] + bb0;
            float z11 = acc[mf][nf][3] + bb1;
            float2 o0, o1;
            if (mat == 0) {
                o0 = make_float2(fsigmoid(z00), fsigmoid(z01));
                o1 = make_float2(fsigmoid(z10), fsigmoid(z11));
            } else {
                o0 = make_float2(ftanh_fast(z00), ftanh_fast(z01));
                o1 = make_float2(ftanh_fast(z10), ftanh_fast(z11));
            }
            *(float2*)(outp + (size_t)row * D_DIM + col)       = o0;
            *(float2*)(outp + (size_t)(row + 8) * D_DIM + col) = o1;
        }
    }
}

// ---------------------------------------------------------------------------
// Sequential scan: one thread per (b,d) channel (16384 chains), depth-8
// register prefetch of (alpha, v) hides DRAM latency behind the serial
// sigmoid recurrence chain.
// out  = d_out[0 : T*B*D]        (h * silu(h))
// hout = d_out[T*B*D : ]         ([h0; h_1..h_T], (T+1)*B*D)
// ---------------------------------------------------------------------------
__global__ __launch_bounds__(256) void scan_kernel(
    const float* __restrict__ h0,
    const float* __restrict__ dg, const float* __restrict__ bg,
    float* __restrict__ out, float* __restrict__ hout)
{
    const int idx = (int)blockIdx.x * 256 + (int)threadIdx.x;  // 0..16383
    const int d   = idx & (D_DIM - 1);
    const float cg1 = dg[d];
    const float cg0 = bg[d];

    float h = h0[idx];
    hout[idx] = h;   // h[0] = h0

    const float* __restrict__ A = g_alpha;
    const float* __restrict__ V = g_v;

    constexpr int PF = 8;
    float pa[PF], pv[PF];
#pragma unroll
    for (int i = 0; i < PF; ++i) {
        pa[i] = A[i * BD + idx];
        pv[i] = V[i * BD + idx];
    }

    for (int t0 = 0; t0 < T_DIM; t0 += PF) {
        float na[PF], nv[PF];
        const int tn = t0 + PF;
        if (tn < T_DIM) {
#pragma unroll
            for (int i = 0; i < PF; ++i) {
                na[i] = __ldg(&A[(tn + i) * BD + idx]);
                nv[i] = __ldg(&V[(tn + i) * BD + idx]);
            }
        } else {
#pragma unroll
            for (int i = 0; i < PF; ++i) { na[i] = 0.0f; nv[i] = 0.0f; }
        }

#pragma unroll
        for (int i = 0; i < PF; ++i) {
            const int t = t0 + i;
            const float gg = 1.0f / (1.0f + __expf(-fmaf(cg1, h, cg0)));
            const float vv = pv[i] * gg;
            h = fmaf(pa[i], h - vv, vv);           // a*h + (1-a)*v*g
            const float s = 1.0f / (1.0f + __expf(-h));
            out[t * BD + idx]        = h * h * s;  // h * silu(h)
            hout[(t + 1) * BD + idx] = h;
        }

#pragma unroll
        for (int i = 0; i < PF; ++i) { pa[i] = na[i]; pv[i] = nv[i]; }
    }
}

// ---------------------------------------------------------------------------
// Launch
// ---------------------------------------------------------------------------
extern "C" void kernel_launch(void* const* d_in, const int* in_sizes, int n_in,
                              void* d_out, int out_size)
{
    (void)in_sizes; (void)n_in; (void)out_size;
    const float* x  = (const float*)d_in[0];   // [T,B,D]
    const float* h0 = (const float*)d_in[1];   // [B,D]
    const float* Wa = (const float*)d_in[2];   // [D,D]
    const float* ba = (const float*)d_in[3];   // [D]
    const float* Wx = (const float*)d_in[4];   // [D,D]
    const float* bv = (const float*)d_in[5];   // [D]
    const float* dg = (const float*)d_in[6];   // [D]
    const float* bg = (const float*)d_in[7];   // [D]

    float* out  = (float*)d_out;
    float* hout = out + (size_t)T_DIM * BD;

    // x fastest dim packs all 16 (n-tile, matrix) CTAs of one m-tile
    // adjacently -> L2 reuse of the x tile within a wave.
    dim3 grid(16, M_DIM / 128, 1);
    gemm_dual_kernel<<<grid, 256>>>(x, Wa, ba, Wx, bv);

    scan_kernel<<<BD / 256, 256>>>(h0, dg, bg, out, hout);
}

// round 7
// speedup vs baseline: 1.4426x; 1.4426x over previous
#include <cuda_runtime.h>
#include <cuda_fp16.h>
#include <cstdint>

// Problem dims
#define T_DIM 2048
#define B_DIM 16
#define D_DIM 1024
#define BD    16384            // B*D
#define M_DIM 32768            // T*B

// ---------------------------------------------------------------------------
// Scratch (device globals: allocation-free)
// ---------------------------------------------------------------------------
__device__ float  g_alpha[(size_t)M_DIM * D_DIM];
__device__ float  g_v[(size_t)M_DIM * D_DIM];
__device__ __half g_xh[(size_t)M_DIM * D_DIM];    // fp16 X
__device__ __half g_wah[(size_t)D_DIM * D_DIM];   // fp16 W_alpha
__device__ __half g_wxh[(size_t)D_DIM * D_DIM];   // fp16 W_x

// ---------------------------------------------------------------------------
// Helpers
// ---------------------------------------------------------------------------
__device__ __forceinline__ uint32_t smem_u32(const void* p) {
    uint32_t a;
    asm("{ .reg .u64 t; cvta.to.shared.u64 t, %1; cvt.u32.u64 %0, t; }"
        : "=r"(a) : "l"(p));
    return a;
}

__device__ __forceinline__ void cp_async16(uint32_t dst, const void* src) {
    asm volatile("cp.async.cg.shared.global [%0], [%1], 16;"
                 :: "r"(dst), "l"(src) : "memory");
}
__device__ __forceinline__ void cp_commit() {
    asm volatile("cp.async.commit_group;" ::: "memory");
}
template <int N>
__device__ __forceinline__ void cp_wait() {
    asm volatile("cp.async.wait_group %0;" :: "n"(N) : "memory");
}

__device__ __forceinline__ void ldsm4(uint32_t& d0, uint32_t& d1, uint32_t& d2,
                                      uint32_t& d3, uint32_t addr) {
    asm volatile("ldmatrix.sync.aligned.m8n8.x4.shared.b16 {%0,%1,%2,%3}, [%4];"
                 : "=r"(d0), "=r"(d1), "=r"(d2), "=r"(d3)
                 : "r"(addr) : "memory");
}

__device__ __forceinline__ void mma_f16(float* c, const uint32_t* a,
                                        const uint32_t* b) {
    asm volatile(
        "mma.sync.aligned.m16n8k16.row.col.f32.f16.f16.f32 "
        "{%0,%1,%2,%3}, {%4,%5,%6,%7}, {%8,%9}, {%0,%1,%2,%3};"
        : "+f"(c[0]), "+f"(c[1]), "+f"(c[2]), "+f"(c[3])
        : "r"(a[0]), "r"(a[1]), "r"(a[2]), "r"(a[3]), "r"(b[0]), "r"(b[1]));
}

__device__ __forceinline__ float fsigmoid(float z) {
    return 1.0f / (1.0f + __expf(-z));
}
__device__ __forceinline__ float ftanh_fast(float z) {
    return 1.0f - 2.0f / (1.0f + __expf(2.0f * z));
}

// ---------------------------------------------------------------------------
// fp32 -> fp16 conversion (one float4 -> 8 bytes per thread)
// ---------------------------------------------------------------------------
__global__ __launch_bounds__(256) void cvt_x_kernel(const float4* __restrict__ x) {
    const int i = (int)blockIdx.x * 256 + (int)threadIdx.x;   // n4 = 8388608
    float4 v = x[i];
    __half2 a = __float22half2_rn(make_float2(v.x, v.y));
    __half2 b = __float22half2_rn(make_float2(v.z, v.w));
    uint2 u; u.x = *(uint32_t*)&a; u.y = *(uint32_t*)&b;
    reinterpret_cast<uint2*>(g_xh)[i] = u;
}
__global__ __launch_bounds__(256) void cvt_w_kernel(const float4* __restrict__ wa,
                                                    const float4* __restrict__ wx) {
    const int i = (int)blockIdx.x * 256 + (int)threadIdx.x;   // n4 = 262144
    float4 v = wa[i];
    __half2 a = __float22half2_rn(make_float2(v.x, v.y));
    __half2 b = __float22half2_rn(make_float2(v.z, v.w));
    uint2 u; u.x = *(uint32_t*)&a; u.y = *(uint32_t*)&b;
    reinterpret_cast<uint2*>(g_wah)[i] = u;
    v = wx[i];
    a = __float22half2_rn(make_float2(v.x, v.y));
    b = __float22half2_rn(make_float2(v.z, v.w));
    u.x = *(uint32_t*)&a; u.y = *(uint32_t*)&b;
    reinterpret_cast<uint2*>(g_wxh)[i] = u;
}

// ---------------------------------------------------------------------------
// fp16 GEMM: C[m,e] = sum_d X[m,d]*W[e,d] (+bias, +activation).
// CTA tile 128x128, BK=32 halves, 3-stage cp.async pipeline.
// 8 warps (2m x 4n), warp tile 64x32, mma m16n8k16.
// Smem: rows of 32 halves padded to 40 (80B stride) -> conflict-free ldmatrix.
// blockIdx.x in [0,16): bit3 = matrix, bits[2:0] = n-tile; x-fast ordering
// shares each X m-tile across 16 CTAs via L2.
// ---------------------------------------------------------------------------
#define NKT      32            // 1024 / 32
#define ROWB     80            // bytes per smem row (32 halves + 8 pad)
#define A_BYTES  (128 * ROWB)  // 10240
#define STAGE_B  (2 * A_BYTES) // A + B = 20480
#define NSTAGE   3
#define GEMM_SMEM (NSTAGE * STAGE_B)   // 61440

__global__ __launch_bounds__(256) void gemm_f16_kernel(
    const float* __restrict__ ba, const float* __restrict__ bv)
{
    extern __shared__ char smem_raw[];
    const uint32_t sbase = smem_u32(smem_raw);

    const int tid  = (int)threadIdx.x;
    const int warp = tid >> 5;
    const int lane = tid & 31;
    const int wm   = warp >> 2;            // 0..1
    const int wn   = warp & 3;             // 0..3

    const int nm  = (int)blockIdx.x;       // 0..15
    const int mat = nm >> 3;
    const int n0  = (nm & 7) * 128;
    const int m0  = (int)blockIdx.y * 128;

    const __half* __restrict__ Xh  = g_xh;
    const __half* __restrict__ Wh  = mat ? g_wxh : g_wah;
    const float* __restrict__ bias = mat ? bv : ba;
    float* __restrict__ outp       = mat ? g_v : g_alpha;

    // staging: 512 16B-chunks per matrix per stage; 2 A + 2 B chunks per thread
    const int r0 = tid >> 2;               // rows 0..63 (and +64)
    const int q0 = tid & 3;                // 16B sub-chunk within 64B row

    auto load_stage = [&](int kt) {
        const uint32_t st = sbase + (uint32_t)(kt % NSTAGE) * STAGE_B;
        const int kh = kt * 32;
        const __half* xa = Xh + (size_t)(m0 + r0) * 1024 + kh + q0 * 8;
        cp_async16(st + (uint32_t)(r0 * ROWB + q0 * 16), xa);
        cp_async16(st + (uint32_t)((r0 + 64) * ROWB + q0 * 16), xa + (size_t)64 * 1024);
        const __half* wb = Wh + (size_t)(n0 + r0) * 1024 + kh + q0 * 8;
        cp_async16(st + A_BYTES + (uint32_t)(r0 * ROWB + q0 * 16), wb);
        cp_async16(st + A_BYTES + (uint32_t)((r0 + 64) * ROWB + q0 * 16),
                   wb + (size_t)64 * 1024);
    };

    // ldmatrix lane geometry (canonical m16n8k16)
    const int rA = lane & 15;                               // row within 16
    const int cA = (lane >> 4) * 16;                        // k half-group (16B)
    const int rB = (lane & 7) + ((lane >> 4) << 3);         // row within 16
    const int cB = ((lane >> 3) & 1) * 16;
    const uint32_t aBase = sbase + (uint32_t)((wm * 64 + rA) * ROWB + cA);
    const uint32_t bBase = sbase + A_BYTES + (uint32_t)((wn * 32 + rB) * ROWB + cB);

    float acc[4][4][4];
#pragma unroll
    for (int mf = 0; mf < 4; ++mf)
#pragma unroll
        for (int nf = 0; nf < 4; ++nf)
#pragma unroll
            for (int q = 0; q < 4; ++q) acc[mf][nf][q] = 0.0f;

    // prologue
    load_stage(0); cp_commit();
    load_stage(1); cp_commit();
    cp_wait<1>();
    __syncthreads();

    for (int kt = 0; kt < NKT; ++kt) {
        if (kt + 2 < NKT) { load_stage(kt + 2); cp_commit(); }

        const uint32_t soff = (uint32_t)(kt % NSTAGE) * STAGE_B;
        const uint32_t sa = aBase + soff;
        const uint32_t sb = bBase + soff;
#pragma unroll
        for (int ks = 0; ks < 2; ++ks) {
            uint32_t af[4][4];
#pragma unroll
            for (int mf = 0; mf < 4; ++mf)
                ldsm4(af[mf][0], af[mf][1], af[mf][2], af[mf][3],
                      sa + (uint32_t)(mf * 16 * ROWB + ks * 32));
            uint32_t bf[4][2];
#pragma unroll
            for (int p = 0; p < 2; ++p)
                ldsm4(bf[2 * p][0], bf[2 * p][1], bf[2 * p + 1][0],
                      bf[2 * p + 1][1], sb + (uint32_t)(p * 16 * ROWB + ks * 32));
#pragma unroll
            for (int mf = 0; mf < 4; ++mf)
#pragma unroll
                for (int nf = 0; nf < 4; ++nf)
                    mma_f16(acc[mf][nf], af[mf], bf[nf]);
        }

        if (kt + 1 < NKT) {
            if (kt + 2 < NKT) cp_wait<1>(); else cp_wait<0>();
            __syncthreads();
        }
    }

    // epilogue: bias + activation, float2 stores (c-frag: rows g/g+8, cols 2tig)
    const int g   = lane >> 2;
    const int tig = lane & 3;
#pragma unroll
    for (int mf = 0; mf < 4; ++mf) {
#pragma unroll
        for (int nf = 0; nf < 4; ++nf) {
            const int row = m0 + wm * 64 + mf * 16 + g;
            const int col = n0 + wn * 32 + nf * 8 + 2 * tig;
            const float bb0 = __ldg(&bias[col]);
            const float bb1 = __ldg(&bias[col + 1]);
            float z00 = acc[mf][nf][0] + bb0;
            float z01 = acc[mf][nf][1] + bb1;
            float z10 = acc[mf][nf][2] + bb0;
            float z11 = acc[mf][nf][3] + bb1;
            float2 o0, o1;
            if (mat == 0) {
                o0 = make_float2(fsigmoid(z00), fsigmoid(z01));
                o1 = make_float2(fsigmoid(z10), fsigmoid(z11));
            } else {
                o0 = make_float2(ftanh_fast(z00), ftanh_fast(z01));
                o1 = make_float2(ftanh_fast(z10), ftanh_fast(z11));
            }
            *(float2*)(outp + (size_t)row * D_DIM + col)       = o0;
            *(float2*)(outp + (size_t)(row + 8) * D_DIM + col) = o1;
        }
    }
}

// ---------------------------------------------------------------------------
// Sequential scan: float2 per thread (2 interleaved chains), 8192 threads
// spread over 256 CTAs x 32 threads (all SMs), PF=8 double-buffer prefetch.
// ---------------------------------------------------------------------------
__global__ __launch_bounds__(32) void scan_kernel(
    const float* __restrict__ h0,
    const float* __restrict__ dg, const float* __restrict__ bg,
    float* __restrict__ out, float* __restrict__ hout)
{
    const int idx = (int)blockIdx.x * 32 + (int)threadIdx.x;   // 0..8191
    const int d0  = (idx * 2) & (D_DIM - 1);                   // even, pair in-bounds

    const float g1x = dg[d0],     g1y = dg[d0 + 1];
    const float g0x = bg[d0],     g0y = bg[d0 + 1];

    float2 h = reinterpret_cast<const float2*>(h0)[idx];
    reinterpret_cast<float2*>(hout)[idx] = h;                  // h[0] = h0

    const float2* __restrict__ A = reinterpret_cast<const float2*>(g_alpha);
    const float2* __restrict__ V = reinterpret_cast<const float2*>(g_v);
    float2* __restrict__ O  = reinterpret_cast<float2*>(out);
    float2* __restrict__ H  = reinterpret_cast<float2*>(hout);
    const int STR = BD / 2;                                    // 8192 float2/step

    constexpr int PF = 8;
    float2 pa[PF], pv[PF];
#pragma unroll
    for (int i = 0; i < PF; ++i) {
        pa[i] = __ldcs(&A[i * STR + idx]);
        pv[i] = __ldcs(&V[i * STR + idx]);
    }

    for (int t0 = 0; t0 < T_DIM; t0 += PF) {
        float2 na[PF], nv[PF];
        const int tn = t0 + PF;
        if (tn < T_DIM) {
#pragma unroll
            for (int i = 0; i < PF; ++i) {
                na[i] = __ldcs(&A[(tn + i) * STR + idx]);
                nv[i] = __ldcs(&V[(tn + i) * STR + idx]);
            }
        } else {
#pragma unroll
            for (int i = 0; i < PF; ++i) {
                na[i] = make_float2(0.f, 0.f); nv[i] = make_float2(0.f, 0.f);
            }
        }

#pragma unroll
        for (int i = 0; i < PF; ++i) {
            const int t = t0 + i;
            const float ggx = fsigmoid(fmaf(g1x, h.x, g0x));
            const float ggy = fsigmoid(fmaf(g1y, h.y, g0y));
            const float vx = pv[i].x * ggx;
            const float vy = pv[i].y * ggy;
            h.x = fmaf(pa[i].x, h.x - vx, vx);     // a*h + (1-a)*v*g
            h.y = fmaf(pa[i].y, h.y - vy, vy);
            const float sx = fsigmoid(h.x);
            const float sy = fsigmoid(h.y);
            float2 o = make_float2(h.x * h.x * sx, h.y * h.y * sy);
            __stcs((float2*)&O[t * STR + idx], o);
            __stcs((float2*)&H[(t + 1) * STR + idx], h);
        }

#pragma unroll
        for (int i = 0; i < PF; ++i) { pa[i] = na[i]; pv[i] = nv[i]; }
    }
}

// ---------------------------------------------------------------------------
// Launch
// ---------------------------------------------------------------------------
extern "C" void kernel_launch(void* const* d_in, const int* in_sizes, int n_in,
                              void* d_out, int out_size)
{
    (void)in_sizes; (void)n_in; (void)out_size;
    const float* x  = (const float*)d_in[0];   // [T,B,D]
    const float* h0 = (const float*)d_in[1];   // [B,D]
    const float* Wa = (const float*)d_in[2];   // [D,D]
    const float* ba = (const float*)d_in[3];   // [D]
    const float* Wx = (const float*)d_in[4];   // [D,D]
    const float* bv = (const float*)d_in[5];   // [D]
    const float* dg = (const float*)d_in[6];   // [D]
    const float* bg = (const float*)d_in[7];   // [D]

    float* out  = (float*)d_out;
    float* hout = out + (size_t)T_DIM * BD;

    cudaFuncSetAttribute(gemm_f16_kernel,
                         cudaFuncAttributeMaxDynamicSharedMemorySize, GEMM_SMEM);

    // 1. fp32 -> fp16 pre-conversion (halves GEMM memory traffic too)
    cvt_x_kernel<<<(M_DIM * D_DIM / 4) / 256, 256>>>((const float4*)x);
    cvt_w_kernel<<<(D_DIM * D_DIM / 4) / 256, 256>>>((const float4*)Wa,
                                                     (const float4*)Wx);

    // 2. dual projections (x-fast: 16 (n,mat) CTAs share X m-tile via L2)
    dim3 grid(16, M_DIM / 128, 1);
    gemm_f16_kernel<<<grid, 256, GEMM_SMEM>>>(ba, bv);

    // 3. recurrence scan
    scan_kernel<<<256, 32>>>(h0, dg, bg, out, hout);
}

// round 8
// speedup vs baseline: 1.8634x; 1.2917x over previous
#include <cuda_runtime.h>
#include <cuda_fp16.h>
#include <cstdint>

// Problem dims
#define T_DIM 2048
#define B_DIM 16
#define D_DIM 1024
#define BD    16384            // B*D
#define M_DIM 32768            // T*B

// ---------------------------------------------------------------------------
// Scratch (device globals: allocation-free)
// ---------------------------------------------------------------------------
__device__ float  g_alpha[(size_t)M_DIM * D_DIM];
__device__ float  g_v[(size_t)M_DIM * D_DIM];
__device__ __half g_xh[(size_t)M_DIM * D_DIM];    // fp16 X
__device__ __half g_wah[(size_t)D_DIM * D_DIM];   // fp16 W_alpha
__device__ __half g_wxh[(size_t)D_DIM * D_DIM];   // fp16 W_x

// ---------------------------------------------------------------------------
// Helpers
// ---------------------------------------------------------------------------
__device__ __forceinline__ uint32_t smem_u32(const void* p) {
    uint32_t a;
    asm("{ .reg .u64 t; cvta.to.shared.u64 t, %1; cvt.u32.u64 %0, t; }"
        : "=r"(a) : "l"(p));
    return a;
}

__device__ __forceinline__ void cp_async16(uint32_t dst, const void* src) {
    asm volatile("cp.async.cg.shared.global [%0], [%1], 16;"
                 :: "r"(dst), "l"(src) : "memory");
}
__device__ __forceinline__ void cp_commit() {
    asm volatile("cp.async.commit_group;" ::: "memory");
}
template <int N>
__device__ __forceinline__ void cp_wait() {
    asm volatile("cp.async.wait_group %0;" :: "n"(N) : "memory");
}

__device__ __forceinline__ void ldsm4(uint32_t& d0, uint32_t& d1, uint32_t& d2,
                                      uint32_t& d3, uint32_t addr) {
    asm volatile("ldmatrix.sync.aligned.m8n8.x4.shared.b16 {%0,%1,%2,%3}, [%4];"
                 : "=r"(d0), "=r"(d1), "=r"(d2), "=r"(d3)
                 : "r"(addr) : "memory");
}

__device__ __forceinline__ void mma_f16(float* c, const uint32_t* a,
                                        const uint32_t* b) {
    asm volatile(
        "mma.sync.aligned.m16n8k16.row.col.f32.f16.f16.f32 "
        "{%0,%1,%2,%3}, {%4,%5,%6,%7}, {%8,%9}, {%0,%1,%2,%3};"
        : "+f"(c[0]), "+f"(c[1]), "+f"(c[2]), "+f"(c[3])
        : "r"(a[0]), "r"(a[1]), "r"(a[2]), "r"(a[3]), "r"(b[0]), "r"(b[1]));
}

__device__ __forceinline__ float fsigmoid(float z) {
    return 1.0f / (1.0f + __expf(-z));
}
__device__ __forceinline__ float ftanh_fast(float z) {
    return 1.0f - 2.0f / (1.0f + __expf(2.0f * z));
}
__device__ __forceinline__ float tanh_hw(float x) {
    float y;
    asm("tanh.approx.f32 %0, %1;" : "=f"(y) : "f"(x));
    return y;
}

// ---------------------------------------------------------------------------
// fp32 -> fp16 conversion
// ---------------------------------------------------------------------------
__global__ __launch_bounds__(256) void cvt_x_kernel(const float4* __restrict__ x) {
    const int i = (int)blockIdx.x * 256 + (int)threadIdx.x;   // n4 = 8388608
    float4 v = x[i];
    __half2 a = __float22half2_rn(make_float2(v.x, v.y));
    __half2 b = __float22half2_rn(make_float2(v.z, v.w));
    uint2 u; u.x = *(uint32_t*)&a; u.y = *(uint32_t*)&b;
    reinterpret_cast<uint2*>(g_xh)[i] = u;
}
__global__ __launch_bounds__(256) void cvt_w_kernel(const float4* __restrict__ wa,
                                                    const float4* __restrict__ wx) {
    const int i = (int)blockIdx.x * 256 + (int)threadIdx.x;   // n4 = 262144
    float4 v = wa[i];
    __half2 a = __float22half2_rn(make_float2(v.x, v.y));
    __half2 b = __float22half2_rn(make_float2(v.z, v.w));
    uint2 u; u.x = *(uint32_t*)&a; u.y = *(uint32_t*)&b;
    reinterpret_cast<uint2*>(g_wah)[i] = u;
    v = wx[i];
    a = __float22half2_rn(make_float2(v.x, v.y));
    b = __float22half2_rn(make_float2(v.z, v.w));
    u.x = *(uint32_t*)&a; u.y = *(uint32_t*)&b;
    reinterpret_cast<uint2*>(g_wxh)[i] = u;
}

// ---------------------------------------------------------------------------
// fp16 GEMM: C[m,e] = sum_d X[m,d]*W[e,d] (+bias, +activation).
// CTA tile 256m x 128n, BK=32 halves, 3-stage cp.async pipeline.
// 8 warps (4m x 2n), warp tile 64x64, mma m16n8k16.
// Smem rows: 32 halves padded to 40 (80B) -> conflict-free ldmatrix.
// blockIdx.x in [0,16): bit3 = matrix, bits[2:0] = n-tile (x-fast: 16 CTAs
// share each X m-tile via L2).
// ---------------------------------------------------------------------------
#define NKT      32            // 1024 / 32
#define ROWB     80
#define A_BYTES  (256 * ROWB)  // 20480
#define B_BYTES  (128 * ROWB)  // 10240
#define STAGE_B  (A_BYTES + B_BYTES)
#define NSTAGE   3
#define GEMM_SMEM (NSTAGE * STAGE_B)   // 92160

__global__ __launch_bounds__(256, 1) void gemm_f16_kernel(
    const float* __restrict__ ba, const float* __restrict__ bv)
{
    extern __shared__ char smem_raw[];
    const uint32_t sbase = smem_u32(smem_raw);

    const int tid  = (int)threadIdx.x;
    const int warp = tid >> 5;
    const int lane = tid & 31;
    const int wm   = warp >> 1;            // 0..3 (64-row slab)
    const int wn   = warp & 1;             // 0..1 (64-col slab)

    const int nm  = (int)blockIdx.x;       // 0..15
    const int mat = nm >> 3;
    const int n0  = (nm & 7) * 128;
    const int m0  = (int)blockIdx.y * 256;

    const __half* __restrict__ Xh  = g_xh;
    const __half* __restrict__ Wh  = mat ? g_wxh : g_wah;
    const float* __restrict__ bias = mat ? bv : ba;
    float* __restrict__ outp       = mat ? g_v : g_alpha;

    const int r0 = tid >> 2;               // 0..63
    const int q0 = tid & 3;

    auto load_stage = [&](int kt) {
        const uint32_t st = sbase + (uint32_t)(kt % NSTAGE) * STAGE_B;
        const int kh = kt * 32;
        const __half* xa = Xh + (size_t)(m0 + r0) * 1024 + kh + q0 * 8;
#pragma unroll
        for (int k = 0; k < 4; ++k)        // A: 256 rows
            cp_async16(st + (uint32_t)((r0 + 64 * k) * ROWB + q0 * 16),
                       xa + (size_t)(64 * k) * 1024);
        const __half* wb = Wh + (size_t)(n0 + r0) * 1024 + kh + q0 * 8;
#pragma unroll
        for (int k = 0; k < 2; ++k)        // B: 128 rows
            cp_async16(st + A_BYTES + (uint32_t)((r0 + 64 * k) * ROWB + q0 * 16),
                       wb + (size_t)(64 * k) * 1024);
    };

    // ldmatrix lane geometry (canonical m16n8k16)
    const int rA = lane & 15;
    const int cA = (lane >> 4) * 16;
    const int rB = (lane & 7) + ((lane >> 4) << 3);
    const int cB = ((lane >> 3) & 1) * 16;
    const uint32_t aBase = sbase + (uint32_t)((wm * 64 + rA) * ROWB + cA);
    const uint32_t bBase = sbase + A_BYTES + (uint32_t)((wn * 64 + rB) * ROWB + cB);

    float acc[4][8][4];
#pragma unroll
    for (int mf = 0; mf < 4; ++mf)
#pragma unroll
        for (int nf = 0; nf < 8; ++nf)
#pragma unroll
            for (int q = 0; q < 4; ++q) acc[mf][nf][q] = 0.0f;

    load_stage(0); cp_commit();
    load_stage(1); cp_commit();
    cp_wait<1>();
    __syncthreads();

    for (int kt = 0; kt < NKT; ++kt) {
        if (kt + 2 < NKT) { load_stage(kt + 2); cp_commit(); }

        const uint32_t soff = (uint32_t)(kt % NSTAGE) * STAGE_B;
        const uint32_t sa = aBase + soff;
        const uint32_t sb = bBase + soff;
#pragma unroll
        for (int ks = 0; ks < 2; ++ks) {
            uint32_t af[4][4];
#pragma unroll
            for (int mf = 0; mf < 4; ++mf)
                ldsm4(af[mf][0], af[mf][1], af[mf][2], af[mf][3],
                      sa + (uint32_t)(mf * 16 * ROWB + ks * 32));
            uint32_t bf[8][2];
#pragma unroll
            for (int p = 0; p < 4; ++p)
                ldsm4(bf[2 * p][0], bf[2 * p][1], bf[2 * p + 1][0],
                      bf[2 * p + 1][1], sb + (uint32_t)(p * 16 * ROWB + ks * 32));
#pragma unroll
            for (int mf = 0; mf < 4; ++mf)
#pragma unroll
                for (int nf = 0; nf < 8; ++nf)
                    mma_f16(acc[mf][nf], af[mf], bf[nf]);
        }

        if (kt + 1 < NKT) {
            if (kt + 2 < NKT) cp_wait<1>(); else cp_wait<0>();
            __syncthreads();
        }
    }

    // epilogue: bias + activation, float2 stores
    const int g   = lane >> 2;
    const int tig = lane & 3;
#pragma unroll
    for (int mf = 0; mf < 4; ++mf) {
#pragma unroll
        for (int nf = 0; nf < 8; ++nf) {
            const int row = m0 + wm * 64 + mf * 16 + g;
            const int col = n0 + wn * 64 + nf * 8 + 2 * tig;
            const float bb0 = __ldg(&bias[col]);
            const float bb1 = __ldg(&bias[col + 1]);
            float z00 = acc[mf][nf][0] + bb0;
            float z01 = acc[mf][nf][1] + bb1;
            float z10 = acc[mf][nf][2] + bb0;
            float z11 = acc[mf][nf][3] + bb1;
            float2 o0, o1;
            if (mat == 0) {
                o0 = make_float2(fsigmoid(z00), fsigmoid(z01));
                o1 = make_float2(fsigmoid(z10), fsigmoid(z11));
            } else {
                o0 = make_float2(ftanh_fast(z00), ftanh_fast(z01));
                o1 = make_float2(ftanh_fast(z10), ftanh_fast(z11));
            }
            *(float2*)(outp + (size_t)row * D_DIM + col)       = o0;
            *(float2*)(outp + (size_t)(row + 8) * D_DIM + col) = o1;
        }
    }
}

// ---------------------------------------------------------------------------
// Sequential scan: 16384 chains, 128 CTAs x 128 threads (1 chain/thread).
// cp.async smem pipeline (5 stages x 8 steps) decouples DRAM latency from the
// serial recurrence; gate sigmoid via HW tanh.approx (chain ~32 cyc/step).
// ---------------------------------------------------------------------------
#define SC_STEPS 8                      // timesteps per stage
#define SC_STAGES 5
#define SC_STAGE_B (SC_STEPS * 128 * 8) // 8KB: A[8][128]f + V[8][128]f

__global__ __launch_bounds__(128) void scan_kernel(
    const float* __restrict__ h0,
    const float* __restrict__ dg, const float* __restrict__ bg,
    float* __restrict__ out, float* __restrict__ hout)
{
    __shared__ __align__(16) char sbuf[SC_STAGES * SC_STAGE_B];  // 40KB

    const int tid  = (int)threadIdx.x;
    const int base = (int)blockIdx.x * 128;
    const int idx  = base + tid;
    const int d    = idx & (D_DIM - 1);

    const float hc1 = 0.5f * dg[d];        // gate: 0.5 + 0.5*tanh(0.5*(c1*h+c0))
    const float hc0 = 0.5f * bg[d];

    float h = h0[idx];
    hout[idx] = h;

    const float* __restrict__ A = g_alpha;
    const float* __restrict__ V = g_v;
    const uint32_t sb0 = smem_u32(sbuf);

    // stage loader: 512 x 16B chunks (A: 256, V: 256), 4 per thread
    auto load_stage = [&](int b) {         // b = stage index (t0 = b*8)
        const uint32_t st = sb0 + (uint32_t)(b % SC_STAGES) * SC_STAGE_B;
        const int t0 = b * SC_STEPS;
#pragma unroll
        for (int j = 0; j < 4; ++j) {
            const int cid  = tid + 128 * j;        // 0..511
            const int arr  = cid >> 8;             // 0=A, 1=V
            const int w    = cid & 255;
            const int step = w >> 5;
            const int ch   = w & 31;
            const float* src = (arr ? V : A) + (size_t)(t0 + step) * BD
                               + base + ch * 4;
            cp_async16(st + (uint32_t)(arr * 4096 + step * 512 + ch * 16), src);
        }
    };

    // prologue: stages 0..3
#pragma unroll
    for (int s = 0; s < SC_STAGES - 1; ++s) { load_stage(s); cp_commit(); }

    const int NB = T_DIM / SC_STEPS;       // 256
    for (int b = 0; b < NB; ++b) {
        cp_wait<SC_STAGES - 2>();          // stage b complete
        __syncthreads();                   // visibility + prev stage consumed
        if (b + SC_STAGES - 1 < NB) load_stage(b + SC_STAGES - 1);
        cp_commit();                       // (empty group in the tail: keeps
                                           //  wait_group bookkeeping exact)

        const uint32_t st = sb0 + (uint32_t)(b % SC_STAGES) * SC_STAGE_B;
        const float* sA = (const float*)(sbuf + (st - sb0));
        const float* sV = sA + 1024;       // +4096B

        float a[SC_STEPS], w[SC_STEPS];
#pragma unroll
        for (int i = 0; i < SC_STEPS; ++i) {
            a[i] = sA[i * 128 + tid];
            const float v = sV[i * 128 + tid];
            w[i] = (1.0f - a[i]) * v;      // off-chain
        }

        const int t0 = b * SC_STEPS;
#pragma unroll
        for (int i = 0; i < SC_STEPS; ++i) {
            const float tg = tanh_hw(fmaf(hc1, h, hc0));
            const float gg = fmaf(0.5f, tg, 0.5f);
            h = fmaf(a[i], h, w[i] * gg);              // a*h + (1-a)*v*g
            const float s = 1.0f / (1.0f + __expf(-h));
            __stcs(&out[(size_t)(t0 + i) * BD + idx], h * h * s);
            __stcs(&hout[(size_t)(t0 + i + 1) * BD + idx], h);
        }
    }
}

// ---------------------------------------------------------------------------
// Launch
// ---------------------------------------------------------------------------
extern "C" void kernel_launch(void* const* d_in, const int* in_sizes, int n_in,
                              void* d_out, int out_size)
{
    (void)in_sizes; (void)n_in; (void)out_size;
    const float* x  = (const float*)d_in[0];   // [T,B,D]
    const float* h0 = (const float*)d_in[1];   // [B,D]
    const float* Wa = (const float*)d_in[2];   // [D,D]
    const float* ba = (const float*)d_in[3];   // [D]
    const float* Wx = (const float*)d_in[4];   // [D,D]
    const float* bv = (const float*)d_in[5];   // [D]
    const float* dg = (const float*)d_in[6];   // [D]
    const float* bg = (const float*)d_in[7];   // [D]

    float* out  = (float*)d_out;
    float* hout = out + (size_t)T_DIM * BD;

    cudaFuncSetAttribute(gemm_f16_kernel,
                         cudaFuncAttributeMaxDynamicSharedMemorySize, GEMM_SMEM);

    // 1. fp32 -> fp16 pre-conversion
    cvt_x_kernel<<<(M_DIM * D_DIM / 4) / 256, 256>>>((const float4*)x);
    cvt_w_kernel<<<(D_DIM * D_DIM / 4) / 256, 256>>>((const float4*)Wa,
                                                     (const float4*)Wx);

    // 2. dual projections (x-fast: 16 (n,mat) CTAs share X m-tile via L2)
    dim3 grid(16, M_DIM / 256, 1);
    gemm_f16_kernel<<<grid, 256, GEMM_SMEM>>>(ba, bv);

    // 3. recurrence scan
    scan_kernel<<<BD / 128, 128>>>(h0, dg, bg, out, hout);
}

// round 9
// speedup vs baseline: 2.5276x; 1.3564x over previous
#include <cuda_runtime.h>
#include <cuda_fp16.h>
#include <cstdint>

// Problem dims
#define T_DIM 2048
#define B_DIM 16
#define D_DIM 1024
#define BD    16384            // B*D
#define M_DIM 32768            // T*B

// ---------------------------------------------------------------------------
// Scratch (device globals: allocation-free)
// ---------------------------------------------------------------------------
__device__ __half g_ah[(size_t)M_DIM * D_DIM];    // fp16 alpha
__device__ __half g_vh[(size_t)M_DIM * D_DIM];    // fp16 v
__device__ __half g_xh[(size_t)M_DIM * D_DIM];    // fp16 X
__device__ __half g_wah[(size_t)D_DIM * D_DIM];   // fp16 W_alpha
__device__ __half g_wxh[(size_t)D_DIM * D_DIM];   // fp16 W_x

// ---------------------------------------------------------------------------
// Helpers
// ---------------------------------------------------------------------------
__device__ __forceinline__ uint32_t smem_u32(const void* p) {
    uint32_t a;
    asm("{ .reg .u64 t; cvta.to.shared.u64 t, %1; cvt.u32.u64 %0, t; }"
        : "=r"(a) : "l"(p));
    return a;
}

__device__ __forceinline__ void cp_async16(uint32_t dst, const void* src) {
    asm volatile("cp.async.cg.shared.global [%0], [%1], 16;"
                 :: "r"(dst), "l"(src) : "memory");
}
__device__ __forceinline__ void cp_commit() {
    asm volatile("cp.async.commit_group;" ::: "memory");
}
template <int N>
__device__ __forceinline__ void cp_wait() {
    asm volatile("cp.async.wait_group %0;" :: "n"(N) : "memory");
}

__device__ __forceinline__ void ldsm4(uint32_t& d0, uint32_t& d1, uint32_t& d2,
                                      uint32_t& d3, uint32_t addr) {
    asm volatile("ldmatrix.sync.aligned.m8n8.x4.shared.b16 {%0,%1,%2,%3}, [%4];"
                 : "=r"(d0), "=r"(d1), "=r"(d2), "=r"(d3)
                 : "r"(addr) : "memory");
}

__device__ __forceinline__ void mma_f16(float* c, const uint32_t* a,
                                        const uint32_t* b) {
    asm volatile(
        "mma.sync.aligned.m16n8k16.row.col.f32.f16.f16.f32 "
        "{%0,%1,%2,%3}, {%4,%5,%6,%7}, {%8,%9}, {%0,%1,%2,%3};"
        : "+f"(c[0]), "+f"(c[1]), "+f"(c[2]), "+f"(c[3])
        : "r"(a[0]), "r"(a[1]), "r"(a[2]), "r"(a[3]), "r"(b[0]), "r"(b[1]));
}

__device__ __forceinline__ float fsigmoid(float z) {
    return 1.0f / (1.0f + __expf(-z));
}
__device__ __forceinline__ float ftanh_fast(float z) {
    return 1.0f - 2.0f / (1.0f + __expf(2.0f * z));
}
__device__ __forceinline__ float tanh_hw(float x) {
    float y;
    asm("tanh.approx.f32 %0, %1;" : "=f"(y) : "f"(x));
    return y;
}

// ---------------------------------------------------------------------------
// fp32 -> fp16 conversion
// ---------------------------------------------------------------------------
__global__ __launch_bounds__(256) void cvt_x_kernel(const float4* __restrict__ x) {
    const int i = (int)blockIdx.x * 256 + (int)threadIdx.x;   // n4 = 8388608
    float4 v = x[i];
    __half2 a = __float22half2_rn(make_float2(v.x, v.y));
    __half2 b = __float22half2_rn(make_float2(v.z, v.w));
    uint2 u; u.x = *(uint32_t*)&a; u.y = *(uint32_t*)&b;
    reinterpret_cast<uint2*>(g_xh)[i] = u;
}
__global__ __launch_bounds__(256) void cvt_w_kernel(const float4* __restrict__ wa,
                                                    const float4* __restrict__ wx) {
    const int i = (int)blockIdx.x * 256 + (int)threadIdx.x;   // n4 = 262144
    float4 v = wa[i];
    __half2 a = __float22half2_rn(make_float2(v.x, v.y));
    __half2 b = __float22half2_rn(make_float2(v.z, v.w));
    uint2 u; u.x = *(uint32_t*)&a; u.y = *(uint32_t*)&b;
    reinterpret_cast<uint2*>(g_wah)[i] = u;
    v = wx[i];
    a = __float22half2_rn(make_float2(v.x, v.y));
    b = __float22half2_rn(make_float2(v.z, v.w));
    u.x = *(uint32_t*)&a; u.y = *(uint32_t*)&b;
    reinterpret_cast<uint2*>(g_wxh)[i] = u;
}

// ---------------------------------------------------------------------------
// fp16 GEMM (R7 config — 2 CTAs/SM): C[m,e] = sum_d X[m,d]*W[e,d] (+bias,+act).
// CTA tile 128x128, BK=32 halves, 3-stage cp.async, 8 warps (2m x 4n),
// warp tile 64x32, mma m16n8k16. Output stored as fp16 (half2).
// blockIdx.x in [0,16): bit3 = matrix, bits[2:0] = n-tile; x-fast ordering
// shares each X m-tile across 16 CTAs via L2.
// ---------------------------------------------------------------------------
#define NKT      32            // 1024 / 32
#define ROWB     80            // 32 halves + 8 pad
#define A_BYTES  (128 * ROWB)  // 10240
#define STAGE_B  (2 * A_BYTES) // 20480
#define NSTAGE   3
#define GEMM_SMEM (NSTAGE * STAGE_B)   // 61440

__global__ __launch_bounds__(256) void gemm_f16_kernel(
    const float* __restrict__ ba, const float* __restrict__ bv)
{
    extern __shared__ char smem_raw[];
    const uint32_t sbase = smem_u32(smem_raw);

    const int tid  = (int)threadIdx.x;
    const int warp = tid >> 5;
    const int lane = tid & 31;
    const int wm   = warp >> 2;            // 0..1
    const int wn   = warp & 3;             // 0..3

    const int nm  = (int)blockIdx.x;       // 0..15
    const int mat = nm >> 3;
    const int n0  = (nm & 7) * 128;
    const int m0  = (int)blockIdx.y * 128;

    const __half* __restrict__ Xh  = g_xh;
    const __half* __restrict__ Wh  = mat ? g_wxh : g_wah;
    const float* __restrict__ bias = mat ? bv : ba;
    __half* __restrict__ outp      = mat ? g_vh : g_ah;

    const int r0 = tid >> 2;               // 0..63
    const int q0 = tid & 3;

    auto load_stage = [&](int kt) {
        const uint32_t st = sbase + (uint32_t)(kt % NSTAGE) * STAGE_B;
        const int kh = kt * 32;
        const __half* xa = Xh + (size_t)(m0 + r0) * 1024 + kh + q0 * 8;
        cp_async16(st + (uint32_t)(r0 * ROWB + q0 * 16), xa);
        cp_async16(st + (uint32_t)((r0 + 64) * ROWB + q0 * 16),
                   xa + (size_t)64 * 1024);
        const __half* wb = Wh + (size_t)(n0 + r0) * 1024 + kh + q0 * 8;
        cp_async16(st + A_BYTES + (uint32_t)(r0 * ROWB + q0 * 16), wb);
        cp_async16(st + A_BYTES + (uint32_t)((r0 + 64) * ROWB + q0 * 16),
                   wb + (size_t)64 * 1024);
    };

    // ldmatrix lane geometry (canonical m16n8k16)
    const int rA = lane & 15;
    const int cA = (lane >> 4) * 16;
    const int rB = (lane & 7) + ((lane >> 4) << 3);
    const int cB = ((lane >> 3) & 1) * 16;
    const uint32_t aBase = sbase + (uint32_t)((wm * 64 + rA) * ROWB + cA);
    const uint32_t bBase = sbase + A_BYTES + (uint32_t)((wn * 32 + rB) * ROWB + cB);

    float acc[4][4][4];
#pragma unroll
    for (int mf = 0; mf < 4; ++mf)
#pragma unroll
        for (int nf = 0; nf < 4; ++nf)
#pragma unroll
            for (int q = 0; q < 4; ++q) acc[mf][nf][q] = 0.0f;

    load_stage(0); cp_commit();
    load_stage(1); cp_commit();
    cp_wait<1>();
    __syncthreads();

    for (int kt = 0; kt < NKT; ++kt) {
        if (kt + 2 < NKT) { load_stage(kt + 2); cp_commit(); }

        const uint32_t soff = (uint32_t)(kt % NSTAGE) * STAGE_B;
        const uint32_t sa = aBase + soff;
        const uint32_t sb = bBase + soff;
#pragma unroll
        for (int ks = 0; ks < 2; ++ks) {
            uint32_t af[4][4];
#pragma unroll
            for (int mf = 0; mf < 4; ++mf)
                ldsm4(af[mf][0], af[mf][1], af[mf][2], af[mf][3],
                      sa + (uint32_t)(mf * 16 * ROWB + ks * 32));
            uint32_t bf[4][2];
#pragma unroll
            for (int p = 0; p < 2; ++p)
                ldsm4(bf[2 * p][0], bf[2 * p][1], bf[2 * p + 1][0],
                      bf[2 * p + 1][1], sb + (uint32_t)(p * 16 * ROWB + ks * 32));
#pragma unroll
            for (int mf = 0; mf < 4; ++mf)
#pragma unroll
                for (int nf = 0; nf < 4; ++nf)
                    mma_f16(acc[mf][nf], af[mf], bf[nf]);
        }

        if (kt + 1 < NKT) {
            if (kt + 2 < NKT) cp_wait<1>(); else cp_wait<0>();
            __syncthreads();
        }
    }

    // epilogue: bias + activation, half2 stores
    const int g   = lane >> 2;
    const int tig = lane & 3;
#pragma unroll
    for (int mf = 0; mf < 4; ++mf) {
#pragma unroll
        for (int nf = 0; nf < 4; ++nf) {
            const int row = m0 + wm * 64 + mf * 16 + g;
            const int col = n0 + wn * 32 + nf * 8 + 2 * tig;
            const float bb0 = __ldg(&bias[col]);
            const float bb1 = __ldg(&bias[col + 1]);
            float z00 = acc[mf][nf][0] + bb0;
            float z01 = acc[mf][nf][1] + bb1;
            float z10 = acc[mf][nf][2] + bb0;
            float z11 = acc[mf][nf][3] + bb1;
            float2 o0, o1;
            if (mat == 0) {
                o0 = make_float2(fsigmoid(z00), fsigmoid(z01));
                o1 = make_float2(fsigmoid(z10), fsigmoid(z11));
            } else {
                o0 = make_float2(ftanh_fast(z00), ftanh_fast(z01));
                o1 = make_float2(ftanh_fast(z10), ftanh_fast(z11));
            }
            *(__half2*)(outp + (size_t)row * D_DIM + col)       = __float22half2_rn(o0);
            *(__half2*)(outp + (size_t)(row + 8) * D_DIM + col) = __float22half2_rn(o1);
        }
    }
}

// ---------------------------------------------------------------------------
// Sequential scan, warp-autonomous: 16384 chains, 128 CTAs x 128 threads.
// Each warp owns 32 consecutive channels and runs its own cp.async ring
// (6 stages x 8 steps x 32 fp16 per array = 1KB/stage) -- no __syncthreads.
// Gate and output sigmoid both via HW tanh.approx.
// ---------------------------------------------------------------------------
#define SC_STEPS  8
#define SC_STG    6
// per-warp stage: A[8][32]h (512B) then V[8][32]h (512B)

__global__ __launch_bounds__(128) void scan_kernel(
    const float* __restrict__ h0,
    const float* __restrict__ dg, const float* __restrict__ bg,
    float* __restrict__ out, float* __restrict__ hout)
{
    __shared__ __align__(16) __half sbuf[4][SC_STG][2][SC_STEPS][32];

    const int tid  = (int)threadIdx.x;
    const int w    = tid >> 5;
    const int lane = tid & 31;
    const int cbase = (int)blockIdx.x * 128 + w * 32;   // warp's channel base
    const int idx   = cbase + lane;
    const int d     = idx & (D_DIM - 1);

    const float hc1 = 0.5f * dg[d];       // gate = 0.5 + 0.5*tanh(0.5*(c1*h+c0))
    const float hc0 = 0.5f * bg[d];

    float h = h0[idx];
    hout[idx] = h;

    const __half* __restrict__ A = g_ah;
    const __half* __restrict__ V = g_vh;
    const uint32_t sw0 = smem_u32(&sbuf[w][0][0][0][0]);

    // per-warp stage loader: 64 x 16B chunks total / 32 lanes = 2 per lane
    auto load_stage = [&](int b) {
        const uint32_t st = sw0 + (uint32_t)(b % SC_STG) * 1024u;
        const int t0 = b * SC_STEPS;
#pragma unroll
        for (int j = 0; j < 2; ++j) {
            const int c    = lane + 32 * j;       // 0..63
            const int arr  = c >> 5;              // 0=A, 1=V
            const int wch  = c & 31;
            const int step = wch >> 2;            // 0..7
            const int part = wch & 3;             // 16B chunk (8 halves)
            const __half* src = (arr ? V : A) + (size_t)(t0 + step) * BD
                                + cbase + part * 8;
            cp_async16(st + (uint32_t)(arr * 512 + step * 64 + part * 16), src);
        }
        cp_commit();
    };

    // prologue: stages 0..4 in flight
#pragma unroll
    for (int s = 0; s < SC_STG - 1; ++s) load_stage(s);

    const int NB = T_DIM / SC_STEPS;      // 256
    for (int b = 0; b < NB; ++b) {
        cp_wait<SC_STG - 2>();            // stage b complete (this lane)
        __syncwarp();                     // cross-lane visibility

        const __half* sA = &sbuf[w][b % SC_STG][0][0][0];
        const __half* sV = &sbuf[w][b % SC_STG][1][0][0];

        float a[SC_STEPS], wv[SC_STEPS];
#pragma unroll
        for (int i = 0; i < SC_STEPS; ++i) {
            a[i] = __half2float(sA[i * 32 + lane]);
            const float v = __half2float(sV[i * 32 + lane]);
            wv[i] = (1.0f - a[i]) * v;    // off-chain
        }
        __syncwarp();                     // lanes done reading before refill

        if (b + SC_STG - 1 < NB) load_stage(b + SC_STG - 1);
        else cp_commit();                 // keep group bookkeeping exact

        const int t0 = b * SC_STEPS;
#pragma unroll
        for (int i = 0; i < SC_STEPS; ++i) {
            const float tg = tanh_hw(fmaf(hc1, h, hc0));
            const float gg = fmaf(0.5f, tg, 0.5f);
            h = fmaf(a[i], h, wv[i] * gg);               // a*h + (1-a)*v*g
            const float sg = fmaf(0.5f, tanh_hw(0.5f * h), 0.5f);   // sigmoid(h)
            __stcs(&out[(size_t)(t0 + i) * BD + idx], h * h * sg);
            __stcs(&hout[(size_t)(t0 + i + 1) * BD + idx], h);
        }
    }
}

// ---------------------------------------------------------------------------
// Launch
// ---------------------------------------------------------------------------
extern "C" void kernel_launch(void* const* d_in, const int* in_sizes, int n_in,
                              void* d_out, int out_size)
{
    (void)in_sizes; (void)n_in; (void)out_size;
    const float* x  = (const float*)d_in[0];   // [T,B,D]
    const float* h0 = (const float*)d_in[1];   // [B,D]
    const float* Wa = (const float*)d_in[2];   // [D,D]
    const float* ba = (const float*)d_in[3];   // [D]
    const float* Wx = (const float*)d_in[4];   // [D,D]
    const float* bv = (const float*)d_in[5];   // [D]
    const float* dg = (const float*)d_in[6];   // [D]
    const float* bg = (const float*)d_in[7];   // [D]

    float* out  = (float*)d_out;
    float* hout = out + (size_t)T_DIM * BD;

    cudaFuncSetAttribute(gemm_f16_kernel,
                         cudaFuncAttributeMaxDynamicSharedMemorySize, GEMM_SMEM);

    // 1. fp32 -> fp16 pre-conversion
    cvt_x_kernel<<<(M_DIM * D_DIM / 4) / 256, 256>>>((const float4*)x);
    cvt_w_kernel<<<(D_DIM * D_DIM / 4) / 256, 256>>>((const float4*)Wa,
                                                     (const float4*)Wx);

    // 2. dual projections (x-fast: 16 (n,mat) CTAs share X m-tile via L2)
    dim3 grid(16, M_DIM / 128, 1);
    gemm_f16_kernel<<<grid, 256, GEMM_SMEM>>>(ba, bv);

    // 3. recurrence scan
    scan_kernel<<<BD / 128, 128>>>(h0, dg, bg, out, hout);
}

// round 10
// speedup vs baseline: 2.6550x; 1.0504x over previous
#include <cuda_runtime.h>
#include <cuda_fp16.h>
#include <cstdint>

// Problem dims
#define T_DIM 2048
#define B_DIM 16
#define D_DIM 1024
#define BD    16384            // B*D
#define M_DIM 32768            // T*B

// ---------------------------------------------------------------------------
// Scratch (device globals: allocation-free)
// ---------------------------------------------------------------------------
__device__ __half g_ah[(size_t)M_DIM * D_DIM];    // fp16 alpha
__device__ __half g_vh[(size_t)M_DIM * D_DIM];    // fp16 v
__device__ __half g_wah[(size_t)D_DIM * D_DIM];   // fp16 W_alpha
__device__ __half g_wxh[(size_t)D_DIM * D_DIM];   // fp16 W_x

// ---------------------------------------------------------------------------
// Helpers
// ---------------------------------------------------------------------------
__device__ __forceinline__ uint32_t smem_u32(const void* p) {
    uint32_t a;
    asm("{ .reg .u64 t; cvta.to.shared.u64 t, %1; cvt.u32.u64 %0, t; }"
        : "=r"(a) : "l"(p));
    return a;
}

__device__ __forceinline__ void cp_async16(uint32_t dst, const void* src) {
    asm volatile("cp.async.cg.shared.global [%0], [%1], 16;"
                 :: "r"(dst), "l"(src) : "memory");
}
__device__ __forceinline__ void cp_commit() {
    asm volatile("cp.async.commit_group;" ::: "memory");
}
template <int N>
__device__ __forceinline__ void cp_wait() {
    asm volatile("cp.async.wait_group %0;" :: "n"(N) : "memory");
}

__device__ __forceinline__ void ldsm4(uint32_t& d0, uint32_t& d1, uint32_t& d2,
                                      uint32_t& d3, uint32_t addr) {
    asm volatile("ldmatrix.sync.aligned.m8n8.x4.shared.b16 {%0,%1,%2,%3}, [%4];"
                 : "=r"(d0), "=r"(d1), "=r"(d2), "=r"(d3)
                 : "r"(addr) : "memory");
}

__device__ __forceinline__ void mma_f16(float* c, const uint32_t* a,
                                        const uint32_t* b) {
    asm volatile(
        "mma.sync.aligned.m16n8k16.row.col.f32.f16.f16.f32 "
        "{%0,%1,%2,%3}, {%4,%5,%6,%7}, {%8,%9}, {%0,%1,%2,%3};"
        : "+f"(c[0]), "+f"(c[1]), "+f"(c[2]), "+f"(c[3])
        : "r"(a[0]), "r"(a[1]), "r"(a[2]), "r"(a[3]), "r"(b[0]), "r"(b[1]));
}

__device__ __forceinline__ float fsigmoid(float z) {
    return __fdividef(1.0f, 1.0f + __expf(-z));
}
__device__ __forceinline__ float ftanh_fast(float z) {
    return 1.0f - __fdividef(2.0f, 1.0f + __expf(2.0f * z));
}
__device__ __forceinline__ float tanh_hw(float x) {
    float y;
    asm("tanh.approx.f32 %0, %1;" : "=f"(y) : "f"(x));
    return y;
}

// ---------------------------------------------------------------------------
// fp32 -> fp16 conversion for the two weight matrices (X converts in-GEMM)
// ---------------------------------------------------------------------------
__global__ __launch_bounds__(256) void cvt_w_kernel(const float4* __restrict__ wa,
                                                    const float4* __restrict__ wx) {
    const int i = (int)blockIdx.x * 256 + (int)threadIdx.x;   // n4 = 262144
    float4 v = wa[i];
    __half2 a = __float22half2_rn(make_float2(v.x, v.y));
    __half2 b = __float22half2_rn(make_float2(v.z, v.w));
    uint2 u; u.x = *(uint32_t*)&a; u.y = *(uint32_t*)&b;
    reinterpret_cast<uint2*>(g_wah)[i] = u;
    v = wx[i];
    a = __float22half2_rn(make_float2(v.x, v.y));
    b = __float22half2_rn(make_float2(v.z, v.w));
    u.x = *(uint32_t*)&a; u.y = *(uint32_t*)&b;
    reinterpret_cast<uint2*>(g_wxh)[i] = u;
}

// ---------------------------------------------------------------------------
// fp16 GEMM: C[m,e] = sum_d X[m,d]*W[e,d] (+bias, +activation).
// CTA 128x128, BK=32, 3 stages, 8 warps (2m x 4n), warp tile 64x32, m16n8k16.
// A-side (X): loaded as fp32 via LDG, converted to fp16 in regs, STS.128
// (removes the standalone cvt_x pass). B-side (W): cp.async fp16.
// Output stored fp16. blockIdx.x in [0,16): bit3 = matrix, bits[2:0] = n-tile
// (x-fast: 16 CTAs share each X m-tile via L2).
// ---------------------------------------------------------------------------
#define NKT      32            // 1024 / 32
#define ROWB     80            // 32 halves + 8 pad
#define A_BYTES  (128 * ROWB)  // 10240
#define STAGE_B  (2 * A_BYTES) // 20480
#define NSTAGE   3
#define GEMM_SMEM (NSTAGE * STAGE_B)   // 61440

__global__ __launch_bounds__(256, 2) void gemm_f16_kernel(
    const float* __restrict__ X,
    const float* __restrict__ ba, const float* __restrict__ bv)
{
    extern __shared__ char smem_raw[];
    const uint32_t sbase = smem_u32(smem_raw);

    const int tid  = (int)threadIdx.x;
    const int warp = tid >> 5;
    const int lane = tid & 31;
    const int wm   = warp >> 2;            // 0..1
    const int wn   = warp & 3;             // 0..3

    const int nm  = (int)blockIdx.x;       // 0..15
    const int mat = nm >> 3;
    const int n0  = (nm & 7) * 128;
    const int m0  = (int)blockIdx.y * 128;

    const __half* __restrict__ Wh  = mat ? g_wxh : g_wah;
    const float* __restrict__ bias = mat ? bv : ba;
    __half* __restrict__ outp      = mat ? g_vh : g_ah;

    const int r0 = tid >> 2;               // 0..63
    const int q0 = tid & 3;

    const float4* __restrict__ Xv = reinterpret_cast<const float4*>(X);

    // A: each thread loads 2 rows x 2 float4 (8 floats/row-chunk) per stage
    auto ldg_A = [&](int kt, float4* r) {
        const size_t base = (size_t)(m0 + r0) * 256 + (size_t)(kt * 8 + q0 * 2);
        r[0] = __ldg(Xv + base);
        r[1] = __ldg(Xv + base + 1);
        r[2] = __ldg(Xv + base + (size_t)64 * 256);
        r[3] = __ldg(Xv + base + (size_t)64 * 256 + 1);
    };
    auto sts_A = [&](int kt, const float4* r) {
        const uint32_t st = sbase + (uint32_t)(kt % NSTAGE) * STAGE_B;
        __half2 ha = __float22half2_rn(make_float2(r[0].x, r[0].y));
        __half2 hb = __float22half2_rn(make_float2(r[0].z, r[0].w));
        __half2 hc = __float22half2_rn(make_float2(r[1].x, r[1].y));
        __half2 hd = __float22half2_rn(make_float2(r[1].z, r[1].w));
        asm volatile("st.shared.v4.b32 [%0], {%1,%2,%3,%4};"
                     :: "r"(st + (uint32_t)(r0 * ROWB + q0 * 16)),
                        "r"(*(uint32_t*)&ha), "r"(*(uint32_t*)&hb),
                        "r"(*(uint32_t*)&hc), "r"(*(uint32_t*)&hd) : "memory");
        ha = __float22half2_rn(make_float2(r[2].x, r[2].y));
        hb = __float22half2_rn(make_float2(r[2].z, r[2].w));
        hc = __float22half2_rn(make_float2(r[3].x, r[3].y));
        hd = __float22half2_rn(make_float2(r[3].z, r[3].w));
        asm volatile("st.shared.v4.b32 [%0], {%1,%2,%3,%4};"
                     :: "r"(st + (uint32_t)((r0 + 64) * ROWB + q0 * 16)),
                        "r"(*(uint32_t*)&ha), "r"(*(uint32_t*)&hb),
                        "r"(*(uint32_t*)&hc), "r"(*(uint32_t*)&hd) : "memory");
    };
    auto load_B = [&](int kt) {
        const uint32_t st = sbase + (uint32_t)(kt % NSTAGE) * STAGE_B;
        const __half* wb = Wh + (size_t)(n0 + r0) * 1024 + kt * 32 + q0 * 8;
        cp_async16(st + A_BYTES + (uint32_t)(r0 * ROWB + q0 * 16), wb);
        cp_async16(st + A_BYTES + (uint32_t)((r0 + 64) * ROWB + q0 * 16),
                   wb + (size_t)64 * 1024);
    };

    // ldmatrix lane geometry (canonical m16n8k16)
    const int rA = lane & 15;
    const int cA = (lane >> 4) * 16;
    const int rB = (lane & 7) + ((lane >> 4) << 3);
    const int cB = ((lane >> 3) & 1) * 16;
    const uint32_t aBase = sbase + (uint32_t)((wm * 64 + rA) * ROWB + cA);
    const uint32_t bBase = sbase + A_BYTES + (uint32_t)((wn * 32 + rB) * ROWB + cB);

    float acc[4][4][4];
#pragma unroll
    for (int mf = 0; mf < 4; ++mf)
#pragma unroll
        for (int nf = 0; nf < 4; ++nf)
#pragma unroll
            for (int q = 0; q < 4; ++q) acc[mf][nf][q] = 0.0f;

    float4 pre[4];

    // prologue: stages 0, 1
    ldg_A(0, pre); load_B(0); cp_commit(); sts_A(0, pre);
    ldg_A(1, pre); load_B(1); cp_commit(); sts_A(1, pre);
    cp_wait<1>();
    __syncthreads();

    for (int kt = 0; kt < NKT; ++kt) {
        if (kt + 2 < NKT) { ldg_A(kt + 2, pre); load_B(kt + 2); cp_commit(); }

        const uint32_t soff = (uint32_t)(kt % NSTAGE) * STAGE_B;
        const uint32_t sa = aBase + soff;
        const uint32_t sb = bBase + soff;
#pragma unroll
        for (int ks = 0; ks < 2; ++ks) {
            uint32_t af[4][4];
#pragma unroll
            for (int mf = 0; mf < 4; ++mf)
                ldsm4(af[mf][0], af[mf][1], af[mf][2], af[mf][3],
                      sa + (uint32_t)(mf * 16 * ROWB + ks * 32));
            uint32_t bf[4][2];
#pragma unroll
            for (int p = 0; p < 2; ++p)
                ldsm4(bf[2 * p][0], bf[2 * p][1], bf[2 * p + 1][0],
                      bf[2 * p + 1][1], sb + (uint32_t)(p * 16 * ROWB + ks * 32));
#pragma unroll
            for (int mf = 0; mf < 4; ++mf)
#pragma unroll
                for (int nf = 0; nf < 4; ++nf)
                    mma_f16(acc[mf][nf], af[mf], bf[nf]);
        }

        if (kt + 2 < NKT) sts_A(kt + 2, pre);   // buffer (kt+2)%3 free since kt-1

        if (kt + 1 < NKT) {
            if (kt + 2 < NKT) cp_wait<1>(); else cp_wait<0>();
            __syncthreads();
        }
    }

    // epilogue: bias + activation, half2 stores
    const int g   = lane >> 2;
    const int tig = lane & 3;
#pragma unroll
    for (int mf = 0; mf < 4; ++mf) {
#pragma unroll
        for (int nf = 0; nf < 4; ++nf) {
            const int row = m0 + wm * 64 + mf * 16 + g;
            const int col = n0 + wn * 32 + nf * 8 + 2 * tig;
            const float bb0 = __ldg(&bias[col]);
            const float bb1 = __ldg(&bias[col + 1]);
            float z00 = acc[mf][nf][0] + bb0;
            float z01 = acc[mf][nf][1] + bb1;
            float z10 = acc[mf][nf][2] + bb0;
            float z11 = acc[mf][nf][3] + bb1;
            float2 o0, o1;
            if (mat == 0) {
                o0 = make_float2(fsigmoid(z00), fsigmoid(z01));
                o1 = make_float2(fsigmoid(z10), fsigmoid(z11));
            } else {
                o0 = make_float2(ftanh_fast(z00), ftanh_fast(z01));
                o1 = make_float2(ftanh_fast(z10), ftanh_fast(z11));
            }
            *(__half2*)(outp + (size_t)row * D_DIM + col)       = __float22half2_rn(o0);
            *(__half2*)(outp + (size_t)(row + 8) * D_DIM + col) = __float22half2_rn(o1);
        }
    }
}

// ---------------------------------------------------------------------------
// Sequential scan, warp-autonomous: 16384 chains, 64 CTAs x 256 threads
// (2 warps/SMSP -> fills the serial-chain stall slots). Each warp owns 32
// channels with its own cp.async ring (6 stages x 8 steps = 1KB/stage/warp).
// Gate via HW tanh.approx (R8-validated); output sigmoid EXACT (expf-based).
// ---------------------------------------------------------------------------
#define SC_STEPS  8
#define SC_STG    6
#define SC_WARPS  8

__global__ __launch_bounds__(256) void scan_kernel(
    const float* __restrict__ h0,
    const float* __restrict__ dg, const float* __restrict__ bg,
    float* __restrict__ out, float* __restrict__ hout)
{
    __shared__ __align__(16) __half sbuf[SC_WARPS][SC_STG][2][SC_STEPS][32]; // 48KB

    const int tid  = (int)threadIdx.x;
    const int w    = tid >> 5;
    const int lane = tid & 31;
    const int cbase = (int)blockIdx.x * 256 + w * 32;   // warp's channel base
    const int idx   = cbase + lane;
    const int d     = idx & (D_DIM - 1);

    const float hc1 = 0.5f * dg[d];       // gate = 0.5 + 0.5*tanh(0.5*(c1*h+c0))
    const float hc0 = 0.5f * bg[d];

    float h = h0[idx];
    hout[idx] = h;

    const __half* __restrict__ A = g_ah;
    const __half* __restrict__ V = g_vh;
    const uint32_t sw0 = smem_u32(&sbuf[w][0][0][0][0]);

    // per-warp stage loader: 64 x 16B chunks / 32 lanes = 2 per lane
    auto load_stage = [&](int b) {
        const uint32_t st = sw0 + (uint32_t)(b % SC_STG) * 1024u;
        const int t0 = b * SC_STEPS;
#pragma unroll
        for (int j = 0; j < 2; ++j) {
            const int c    = lane + 32 * j;       // 0..63
            const int arr  = c >> 5;              // 0=A, 1=V
            const int wch  = c & 31;
            const int step = wch >> 2;            // 0..7
            const int part = wch & 3;             // 16B chunk (8 halves)
            const __half* src = (arr ? V : A) + (size_t)(t0 + step) * BD
                                + cbase + part * 8;
            cp_async16(st + (uint32_t)(arr * 512 + step * 64 + part * 16), src);
        }
        cp_commit();
    };

    // prologue: stages 0..4 in flight
#pragma unroll
    for (int s = 0; s < SC_STG - 1; ++s) load_stage(s);

    const int NB = T_DIM / SC_STEPS;      // 256
    for (int b = 0; b < NB; ++b) {
        cp_wait<SC_STG - 2>();            // stage b complete
        __syncwarp();                     // cross-lane visibility

        const __half* sA = &sbuf[w][b % SC_STG][0][0][0];
        const __half* sV = &sbuf[w][b % SC_STG][1][0][0];

        float a[SC_STEPS], wv[SC_STEPS];
#pragma unroll
        for (int i = 0; i < SC_STEPS; ++i) {
            a[i] = __half2float(sA[i * 32 + lane]);
            const float v = __half2float(sV[i * 32 + lane]);
            wv[i] = (1.0f - a[i]) * v;    // off-chain
        }
        __syncwarp();                     // lanes done reading before refill

        if (b + SC_STG - 1 < NB) load_stage(b + SC_STG - 1);
        else cp_commit();                 // keep group bookkeeping exact

        const int t0 = b * SC_STEPS;
#pragma unroll
        for (int i = 0; i < SC_STEPS; ++i) {
            const float tg = tanh_hw(fmaf(hc1, h, hc0));
            const float gg = fmaf(0.5f, tg, 0.5f);
            h = fmaf(a[i], h, wv[i] * gg);               // a*h + (1-a)*v*g
            const float sg = __fdividef(1.0f, 1.0f + __expf(-h));  // exact sigmoid
            __stcs(&out[(size_t)(t0 + i) * BD + idx], h * h * sg);
            __stcs(&hout[(size_t)(t0 + i + 1) * BD + idx], h);
        }
    }
}

// ---------------------------------------------------------------------------
// Launch
// ---------------------------------------------------------------------------
extern "C" void kernel_launch(void* const* d_in, const int* in_sizes, int n_in,
                              void* d_out, int out_size)
{
    (void)in_sizes; (void)n_in; (void)out_size;
    const float* x  = (const float*)d_in[0];   // [T,B,D]
    const float* h0 = (const float*)d_in[1];   // [B,D]
    const float* Wa = (const float*)d_in[2];   // [D,D]
    const float* ba = (const float*)d_in[3];   // [D]
    const float* Wx = (const float*)d_in[4];   // [D,D]
    const float* bv = (const float*)d_in[5];   // [D]
    const float* dg = (const float*)d_in[6];   // [D]
    const float* bg = (const float*)d_in[7];   // [D]

    float* out  = (float*)d_out;
    float* hout = out + (size_t)T_DIM * BD;

    cudaFuncSetAttribute(gemm_f16_kernel,
                         cudaFuncAttributeMaxDynamicSharedMemorySize, GEMM_SMEM);

    // 1. weights fp32 -> fp16 (X converts inside the GEMM)
    cvt_w_kernel<<<(D_DIM * D_DIM / 4) / 256, 256>>>((const float4*)Wa,
                                                     (const float4*)Wx);

    // 2. dual projections (x-fast: 16 (n,mat) CTAs share X m-tile via L2)
    dim3 grid(16, M_DIM / 128, 1);
    gemm_f16_kernel<<<grid, 256, GEMM_SMEM>>>(x, ba, bv);

    // 3. recurrence scan
    scan_kernel<<<BD / 256, 256>>>(h0, dg, bg, out, hout);
}

// round 11
// speedup vs baseline: 2.7029x; 1.0180x over previous
#include <cuda_runtime.h>
#include <cuda_fp16.h>
#include <cstdint>

// Problem dims
#define T_DIM 2048
#define B_DIM 16
#define D_DIM 1024
#define BD    16384            // B*D
#define M_DIM 32768            // T*B

// ---------------------------------------------------------------------------
// Scratch (device globals: allocation-free)
// g_wh stores w = 1 - alpha = sigmoid(-z): near 0.12 the fp16 grid is ~4x
// finer than near alpha~0.88, cutting the recurrence's dominant error term.
// ---------------------------------------------------------------------------
__device__ __half g_wh[(size_t)M_DIM * D_DIM];    // fp16 (1 - alpha)
__device__ __half g_vh[(size_t)M_DIM * D_DIM];    // fp16 v
__device__ __half g_wah[(size_t)D_DIM * D_DIM];   // fp16 W_alpha
__device__ __half g_wxh[(size_t)D_DIM * D_DIM];   // fp16 W_x

// ---------------------------------------------------------------------------
// Helpers
// ---------------------------------------------------------------------------
__device__ __forceinline__ uint32_t smem_u32(const void* p) {
    uint32_t a;
    asm("{ .reg .u64 t; cvta.to.shared.u64 t, %1; cvt.u32.u64 %0, t; }"
        : "=r"(a) : "l"(p));
    return a;
}

__device__ __forceinline__ void cp_async16(uint32_t dst, const void* src) {
    asm volatile("cp.async.cg.shared.global [%0], [%1], 16;"
                 :: "r"(dst), "l"(src) : "memory");
}
__device__ __forceinline__ void cp_commit() {
    asm volatile("cp.async.commit_group;" ::: "memory");
}
template <int N>
__device__ __forceinline__ void cp_wait() {
    asm volatile("cp.async.wait_group %0;" :: "n"(N) : "memory");
}

__device__ __forceinline__ void ldsm4(uint32_t& d0, uint32_t& d1, uint32_t& d2,
                                      uint32_t& d3, uint32_t addr) {
    asm volatile("ldmatrix.sync.aligned.m8n8.x4.shared.b16 {%0,%1,%2,%3}, [%4];"
                 : "=r"(d0), "=r"(d1), "=r"(d2), "=r"(d3)
                 : "r"(addr) : "memory");
}

__device__ __forceinline__ void mma_f16(float* c, const uint32_t* a,
                                        const uint32_t* b) {
    asm volatile(
        "mma.sync.aligned.m16n8k16.row.col.f32.f16.f16.f32 "
        "{%0,%1,%2,%3}, {%4,%5,%6,%7}, {%8,%9}, {%0,%1,%2,%3};"
        : "+f"(c[0]), "+f"(c[1]), "+f"(c[2]), "+f"(c[3])
        : "r"(a[0]), "r"(a[1]), "r"(a[2]), "r"(a[3]), "r"(b[0]), "r"(b[1]));
}

__device__ __forceinline__ float fsigmoid(float z) {
    return __fdividef(1.0f, 1.0f + __expf(-z));
}
__device__ __forceinline__ float ftanh_fast(float z) {
    return 1.0f - __fdividef(2.0f, 1.0f + __expf(2.0f * z));
}
__device__ __forceinline__ float tanh_hw(float x) {
    float y;
    asm("tanh.approx.f32 %0, %1;" : "=f"(y) : "f"(x));
    return y;
}

// ---------------------------------------------------------------------------
// fp32 -> fp16 conversion for the two weight matrices (X converts in-GEMM)
// ---------------------------------------------------------------------------
__global__ __launch_bounds__(256) void cvt_w_kernel(const float4* __restrict__ wa,
                                                    const float4* __restrict__ wx) {
    const int i = (int)blockIdx.x * 256 + (int)threadIdx.x;   // n4 = 262144
    float4 v = wa[i];
    __half2 a = __float22half2_rn(make_float2(v.x, v.y));
    __half2 b = __float22half2_rn(make_float2(v.z, v.w));
    uint2 u; u.x = *(uint32_t*)&a; u.y = *(uint32_t*)&b;
    reinterpret_cast<uint2*>(g_wah)[i] = u;
    v = wx[i];
    a = __float22half2_rn(make_float2(v.x, v.y));
    b = __float22half2_rn(make_float2(v.z, v.w));
    u.x = *(uint32_t*)&a; u.y = *(uint32_t*)&b;
    reinterpret_cast<uint2*>(g_wxh)[i] = u;
}

// ---------------------------------------------------------------------------
// fp16 GEMM: C[m,e] = sum_d X[m,d]*W[e,d] (+bias, +activation).
// CTA 128x128, BK=32, 4 stages, 8 warps (2m x 4n), warp tile 64x32, m16n8k16.
// A-side (X): fp32 LDG -> reg cvt -> STS.128. B-side (W): cp.async fp16.
// mat==0 stores w = sigmoid(-z) = 1 - alpha; mat==1 stores tanh(z).
// blockIdx.x in [0,16): bit3 = matrix, bits[2:0] = n-tile (x-fast: 16 CTAs
// share each X m-tile via L2).
// ---------------------------------------------------------------------------
#define NKT      32            // 1024 / 32
#define ROWB     80            // 32 halves + 8 pad
#define A_BYTES  (128 * ROWB)  // 10240
#define STAGE_B  (2 * A_BYTES) // 20480
#define NSTAGE   4
#define GEMM_SMEM (NSTAGE * STAGE_B)   // 81920

__global__ __launch_bounds__(256, 2) void gemm_f16_kernel(
    const float* __restrict__ X,
    const float* __restrict__ ba, const float* __restrict__ bv)
{
    extern __shared__ char smem_raw[];
    const uint32_t sbase = smem_u32(smem_raw);

    const int tid  = (int)threadIdx.x;
    const int warp = tid >> 5;
    const int lane = tid & 31;
    const int wm   = warp >> 2;            // 0..1
    const int wn   = warp & 3;             // 0..3

    const int nm  = (int)blockIdx.x;       // 0..15
    const int mat = nm >> 3;
    const int n0  = (nm & 7) * 128;
    const int m0  = (int)blockIdx.y * 128;

    const __half* __restrict__ Wh  = mat ? g_wxh : g_wah;
    const float* __restrict__ bias = mat ? bv : ba;
    __half* __restrict__ outp      = mat ? g_vh : g_wh;

    const int r0 = tid >> 2;               // 0..63
    const int q0 = tid & 3;

    const float4* __restrict__ Xv = reinterpret_cast<const float4*>(X);

    auto ldg_A = [&](int kt, float4* r) {
        const size_t base = (size_t)(m0 + r0) * 256 + (size_t)(kt * 8 + q0 * 2);
        r[0] = __ldg(Xv + base);
        r[1] = __ldg(Xv + base + 1);
        r[2] = __ldg(Xv + base + (size_t)64 * 256);
        r[3] = __ldg(Xv + base + (size_t)64 * 256 + 1);
    };
    auto sts_A = [&](int kt, const float4* r) {
        const uint32_t st = sbase + (uint32_t)(kt % NSTAGE) * STAGE_B;
        __half2 ha = __float22half2_rn(make_float2(r[0].x, r[0].y));
        __half2 hb = __float22half2_rn(make_float2(r[0].z, r[0].w));
        __half2 hc = __float22half2_rn(make_float2(r[1].x, r[1].y));
        __half2 hd = __float22half2_rn(make_float2(r[1].z, r[1].w));
        asm volatile("st.shared.v4.b32 [%0], {%1,%2,%3,%4};"
                     :: "r"(st + (uint32_t)(r0 * ROWB + q0 * 16)),
                        "r"(*(uint32_t*)&ha), "r"(*(uint32_t*)&hb),
                        "r"(*(uint32_t*)&hc), "r"(*(uint32_t*)&hd) : "memory");
        ha = __float22half2_rn(make_float2(r[2].x, r[2].y));
        hb = __float22half2_rn(make_float2(r[2].z, r[2].w));
        hc = __float22half2_rn(make_float2(r[3].x, r[3].y));
        hd = __float22half2_rn(make_float2(r[3].z, r[3].w));
        asm volatile("st.shared.v4.b32 [%0], {%1,%2,%3,%4};"
                     :: "r"(st + (uint32_t)((r0 + 64) * ROWB + q0 * 16)),
                        "r"(*(uint32_t*)&ha), "r"(*(uint32_t*)&hb),
                        "r"(*(uint32_t*)&hc), "r"(*(uint32_t*)&hd) : "memory");
    };
    auto load_B = [&](int kt) {
        const uint32_t st = sbase + (uint32_t)(kt % NSTAGE) * STAGE_B;
        const __half* wb = Wh + (size_t)(n0 + r0) * 1024 + kt * 32 + q0 * 8;
        cp_async16(st + A_BYTES + (uint32_t)(r0 * ROWB + q0 * 16), wb);
        cp_async16(st + A_BYTES + (uint32_t)((r0 + 64) * ROWB + q0 * 16),
                   wb + (size_t)64 * 1024);
    };

    // ldmatrix lane geometry (canonical m16n8k16)
    const int rA = lane & 15;
    const int cA = (lane >> 4) * 16;
    const int rB = (lane & 7) + ((lane >> 4) << 3);
    const int cB = ((lane >> 3) & 1) * 16;
    const uint32_t aBase = sbase + (uint32_t)((wm * 64 + rA) * ROWB + cA);
    const uint32_t bBase = sbase + A_BYTES + (uint32_t)((wn * 32 + rB) * ROWB + cB);

    float acc[4][4][4];
#pragma unroll
    for (int mf = 0; mf < 4; ++mf)
#pragma unroll
        for (int nf = 0; nf < 4; ++nf)
#pragma unroll
            for (int q = 0; q < 4; ++q) acc[mf][nf][q] = 0.0f;

    float4 pre[4];

    // prologue: stages 0..2 in flight, 0..1 complete before loop
    ldg_A(0, pre); load_B(0); cp_commit(); sts_A(0, pre);
    ldg_A(1, pre); load_B(1); cp_commit(); sts_A(1, pre);
    ldg_A(2, pre); load_B(2); cp_commit(); sts_A(2, pre);
    cp_wait<2>();
    __syncthreads();

    for (int kt = 0; kt < NKT; ++kt) {
        if (kt + 3 < NKT) { ldg_A(kt + 3, pre); load_B(kt + 3); cp_commit(); }

        const uint32_t soff = (uint32_t)(kt % NSTAGE) * STAGE_B;
        const uint32_t sa = aBase + soff;
        const uint32_t sb = bBase + soff;
#pragma unroll
        for (int ks = 0; ks < 2; ++ks) {
            uint32_t af[4][4];
#pragma unroll
            for (int mf = 0; mf < 4; ++mf)
                ldsm4(af[mf][0], af[mf][1], af[mf][2], af[mf][3],
                      sa + (uint32_t)(mf * 16 * ROWB + ks * 32));
            uint32_t bf[4][2];
#pragma unroll
            for (int p = 0; p < 2; ++p)
                ldsm4(bf[2 * p][0], bf[2 * p][1], bf[2 * p + 1][0],
                      bf[2 * p + 1][1], sb + (uint32_t)(p * 16 * ROWB + ks * 32));
#pragma unroll
            for (int mf = 0; mf < 4; ++mf)
#pragma unroll
                for (int nf = 0; nf < 4; ++nf)
                    mma_f16(acc[mf][nf], af[mf], bf[nf]);
        }

        if (kt + 3 < NKT) sts_A(kt + 3, pre);   // buffer (kt+3)%4 == (kt-1)%4

        if (kt + 1 < NKT) {
            if (kt + 3 < NKT)      cp_wait<2>();
            else if (kt + 2 < NKT) cp_wait<1>();
            else                   cp_wait<0>();
            __syncthreads();
        }
    }

    // epilogue: bias + activation, half2 stores
    const int g   = lane >> 2;
    const int tig = lane & 3;
#pragma unroll
    for (int mf = 0; mf < 4; ++mf) {
#pragma unroll
        for (int nf = 0; nf < 4; ++nf) {
            const int row = m0 + wm * 64 + mf * 16 + g;
            const int col = n0 + wn * 32 + nf * 8 + 2 * tig;
            const float bb0 = __ldg(&bias[col]);
            const float bb1 = __ldg(&bias[col + 1]);
            float z00 = acc[mf][nf][0] + bb0;
            float z01 = acc[mf][nf][1] + bb1;
            float z10 = acc[mf][nf][2] + bb0;
            float z11 = acc[mf][nf][3] + bb1;
            float2 o0, o1;
            if (mat == 0) {        // store w = 1 - alpha = sigmoid(-z)
                o0 = make_float2(fsigmoid(-z00), fsigmoid(-z01));
                o1 = make_float2(fsigmoid(-z10), fsigmoid(-z11));
            } else {               // store v = tanh(z)
                o0 = make_float2(ftanh_fast(z00), ftanh_fast(z01));
                o1 = make_float2(ftanh_fast(z10), ftanh_fast(z11));
            }
            *(__half2*)(outp + (size_t)row * D_DIM + col)       = __float22half2_rn(o0);
            *(__half2*)(outp + (size_t)(row + 8) * D_DIM + col) = __float22half2_rn(o1);
        }
    }
}

// ---------------------------------------------------------------------------
// Sequential scan, warp-autonomous: 16384 chains, 128 CTAs x 128 threads
// (R9-measured best spread). Each warp owns 32 channels with its own
// cp.async ring (6 stages x 8 steps = 1KB/stage/warp). Both sigmoids via HW
// tanh.approx (R9 vs R10 showed zero rel_err delta for the output one).
// a = 1 - w reconstructed in fp32 from the finely-quantized fp16 w.
// ---------------------------------------------------------------------------
#define SC_STEPS  8
#define SC_STG    6
#define SC_WARPS  4

__global__ __launch_bounds__(128) void scan_kernel(
    const float* __restrict__ h0,
    const float* __restrict__ dg, const float* __restrict__ bg,
    float* __restrict__ out, float* __restrict__ hout)
{
    __shared__ __align__(16) __half sbuf[SC_WARPS][SC_STG][2][SC_STEPS][32]; // 24KB

    const int tid  = (int)threadIdx.x;
    const int w    = tid >> 5;
    const int lane = tid & 31;
    const int cbase = (int)blockIdx.x * 128 + w * 32;   // warp's channel base
    const int idx   = cbase + lane;
    const int d     = idx & (D_DIM - 1);

    const float hc1 = 0.5f * dg[d];       // gate = 0.5 + 0.5*tanh(0.5*(c1*h+c0))
    const float hc0 = 0.5f * bg[d];

    float h = h0[idx];
    hout[idx] = h;

    const __half* __restrict__ Wp = g_wh;
    const __half* __restrict__ V  = g_vh;
    const uint32_t sw0 = smem_u32(&sbuf[w][0][0][0][0]);

    // per-warp stage loader: 64 x 16B chunks / 32 lanes = 2 per lane
    auto load_stage = [&](int b) {
        const uint32_t st = sw0 + (uint32_t)(b % SC_STG) * 1024u;
        const int t0 = b * SC_STEPS;
#pragma unroll
        for (int j = 0; j < 2; ++j) {
            const int c    = lane + 32 * j;       // 0..63
            const int arr  = c >> 5;              // 0=W, 1=V
            const int wch  = c & 31;
            const int step = wch >> 2;            // 0..7
            const int part = wch & 3;             // 16B chunk (8 halves)
            const __half* src = (arr ? V : Wp) + (size_t)(t0 + step) * BD
                                + cbase + part * 8;
            cp_async16(st + (uint32_t)(arr * 512 + step * 64 + part * 16), src);
        }
        cp_commit();
    };

    // prologue: stages 0..4 in flight
#pragma unroll
    for (int s = 0; s < SC_STG - 1; ++s) load_stage(s);

    const int NB = T_DIM / SC_STEPS;      // 256
    for (int b = 0; b < NB; ++b) {
        cp_wait<SC_STG - 2>();            // stage b complete
        __syncwarp();                     // cross-lane visibility

        const __half* sW = &sbuf[w][b % SC_STG][0][0][0];
        const __half* sV = &sbuf[w][b % SC_STG][1][0][0];

        float a[SC_STEPS], wv[SC_STEPS];
#pragma unroll
        for (int i = 0; i < SC_STEPS; ++i) {
            const float wq = __half2float(sW[i * 32 + lane]);   // w = 1-alpha
            const float v  = __half2float(sV[i * 32 + lane]);
            a[i]  = 1.0f - wq;            // alpha, fp32-exact from fine w grid
            wv[i] = wq * v;               // (1-alpha)*v, off-chain
        }
        __syncwarp();                     // lanes done reading before refill

        if (b + SC_STG - 1 < NB) load_stage(b + SC_STG - 1);
        else cp_commit();                 // keep group bookkeeping exact

        const int t0 = b * SC_STEPS;
#pragma unroll
        for (int i = 0; i < SC_STEPS; ++i) {
            const float tg = tanh_hw(fmaf(hc1, h, hc0));
            const float gg = fmaf(0.5f, tg, 0.5f);
            h = fmaf(a[i], h, wv[i] * gg);               // a*h + (1-a)*v*g
            const float sg = fmaf(0.5f, tanh_hw(0.5f * h), 0.5f);  // sigmoid(h)
            __stcs(&out[(size_t)(t0 + i) * BD + idx], h * h * sg);
            __stcs(&hout[(size_t)(t0 + i + 1) * BD + idx], h);
        }
    }
}

// ---------------------------------------------------------------------------
// Launch
// ---------------------------------------------------------------------------
extern "C" void kernel_launch(void* const* d_in, const int* in_sizes, int n_in,
                              void* d_out, int out_size)
{
    (void)in_sizes; (void)n_in; (void)out_size;
    const float* x  = (const float*)d_in[0];   // [T,B,D]
    const float* h0 = (const float*)d_in[1];   // [B,D]
    const float* Wa = (const float*)d_in[2];   // [D,D]
    const float* ba = (const float*)d_in[3];   // [D]
    const float* Wx = (const float*)d_in[4];   // [D,D]
    const float* bv = (const float*)d_in[5];   // [D]
    const float* dg = (const float*)d_in[6];   // [D]
    const float* bg = (const float*)d_in[7];   // [D]

    float* out  = (float*)d_out;
    float* hout = out + (size_t)T_DIM * BD;

    cudaFuncSetAttribute(gemm_f16_kernel,
                         cudaFuncAttributeMaxDynamicSharedMemorySize, GEMM_SMEM);

    // 1. weights fp32 -> fp16 (X converts inside the GEMM)
    cvt_w_kernel<<<(D_DIM * D_DIM / 4) / 256, 256>>>((const float4*)Wa,
                                                     (const float4*)Wx);

    // 2. dual projections (x-fast: 16 (n,mat) CTAs share X m-tile via L2)
    dim3 grid(16, M_DIM / 128, 1);
    gemm_f16_kernel<<<grid, 256, GEMM_SMEM>>>(x, ba, bv);

    // 3. recurrence scan
    scan_kernel<<<BD / 128, 128>>>(h0, dg, bg, out, hout);
}